// round 1
// baseline (speedup 1.0000x reference)
#include <cuda_runtime.h>

#define NB 4096
#define NT 32
#define NH 16
#define NHS 32
#define NE 512
#define NM (NB*NT)          // 131072 rows for both big GEMMs

// Scratch: Q/K/V as [b][h][t][d], ATT transposed as [b][d][h*T+t]
__device__ float g_q[(size_t)NB*NH*NT*NHS];
__device__ float g_k[(size_t)NB*NH*NT*NHS];
__device__ float g_v[(size_t)NB*NH*NT*NHS];
__device__ float g_at[(size_t)NB*NHS*NH*NT];

// ---------------------------------------------------------------------------
// Kernel A: QKV projections.  C[m,n] = sum_e X[m,e] * W[n,e]
// X: [131072, 512] row-major, W: [512, 512] row-major (K-contiguous both).
// blockIdx.z selects {Wq, Wk, Wv}; output scattered into [b,h,t,d] layout.
// 128x128 block tile, BK=8, 256 threads, 8x8 microtile.
// ---------------------------------------------------------------------------
__global__ __launch_bounds__(256) void qkv_kernel(
    const float* __restrict__ x,
    const float* __restrict__ Wq,
    const float* __restrict__ Wk,
    const float* __restrict__ Wv)
{
    const int zz = blockIdx.z;
    const float* Wm = (zz == 0) ? Wq : ((zz == 1) ? Wk : Wv);
    float* out = (zz == 0) ? g_q : ((zz == 1) ? g_k : g_v);

    __shared__ float As[8][128];
    __shared__ float Bs[8][128];

    const int tid = threadIdx.x;
    const int tx = tid & 15;          // 0..15  -> 8 cols each
    const int ty = tid >> 4;          // 0..15  -> 8 rows each
    const int m0 = blockIdx.y * 128;
    const int n0 = blockIdx.x * 128;

    const int lrow = tid >> 1;        // 0..127
    const int lk   = (tid & 1) * 4;   // 0 or 4

    const float* aptr = x  + (size_t)(m0 + lrow) * NE + lk;
    const float* bptr = Wm + (size_t)(n0 + lrow) * NE + lk;

    float acc[8][8];
    #pragma unroll
    for (int i = 0; i < 8; i++)
        #pragma unroll
        for (int j = 0; j < 8; j++) acc[i][j] = 0.0f;

    for (int k0 = 0; k0 < NE; k0 += 8) {
        float4 av = *(const float4*)(aptr + k0);
        float4 bv = *(const float4*)(bptr + k0);
        __syncthreads();
        As[lk + 0][lrow] = av.x; As[lk + 1][lrow] = av.y;
        As[lk + 2][lrow] = av.z; As[lk + 3][lrow] = av.w;
        Bs[lk + 0][lrow] = bv.x; Bs[lk + 1][lrow] = bv.y;
        Bs[lk + 2][lrow] = bv.z; Bs[lk + 3][lrow] = bv.w;
        __syncthreads();
        #pragma unroll
        for (int kk = 0; kk < 8; kk++) {
            float4 a0 = *(const float4*)&As[kk][ty * 8];
            float4 a1 = *(const float4*)&As[kk][ty * 8 + 4];
            float4 b0 = *(const float4*)&Bs[kk][tx * 8];
            float4 b1 = *(const float4*)&Bs[kk][tx * 8 + 4];
            float a[8] = {a0.x, a0.y, a0.z, a0.w, a1.x, a1.y, a1.z, a1.w};
            float b[8] = {b0.x, b0.y, b0.z, b0.w, b1.x, b1.y, b1.z, b1.w};
            #pragma unroll
            for (int i = 0; i < 8; i++)
                #pragma unroll
                for (int j = 0; j < 8; j++)
                    acc[i][j] = fmaf(a[i], b[j], acc[i][j]);
        }
    }

    // Epilogue: scatter into [b,h,t,d]; n chunks of 8 never cross head boundary.
    #pragma unroll
    for (int i = 0; i < 8; i++) {
        int m = m0 + ty * 8 + i;
        int bb = m >> 5, tt = m & 31;
        #pragma unroll
        for (int j = 0; j < 8; j += 4) {
            int n = n0 + tx * 8 + j;
            int hh = n >> 5, dd = n & 31;
            float4 v4 = make_float4(acc[i][j], acc[i][j+1], acc[i][j+2], acc[i][j+3]);
            *(float4*)(out + ((size_t)((bb * NH + hh) * NT + tt)) * NHS + dd) = v4;
        }
    }
}

// ---------------------------------------------------------------------------
// Kernel B: per-(b,h) 32x32x32 causal attention, output written TRANSPOSED
// into g_at[b][d][h*32+t] so the final projection is a plain K-major GEMM.
// 256 threads = 8 warps; each warp owns 4 score rows.
// ---------------------------------------------------------------------------
__global__ __launch_bounds__(256) void attn_kernel()
{
    __shared__ float qs[32][33];
    __shared__ float ks[32][33];
    __shared__ float vs[32][33];
    __shared__ float os[32][33];   // os[d][t]

    const int bh = blockIdx.x;              // b*NH + h
    const int b = bh >> 4, h = bh & 15;
    const int tid = threadIdx.x;
    const size_t base = (size_t)bh * NT * NHS;

    for (int i = tid; i < NT * NHS; i += 256) {
        int t = i >> 5, d = i & 31;
        qs[t][d] = g_q[base + i];
        ks[t][d] = g_k[base + i];
        vs[t][d] = g_v[base + i];
    }
    __syncthreads();

    const int w = tid >> 5, lane = tid & 31;
    const float scale = 0.17677669529663687f;   // 1/sqrt(32)

    #pragma unroll
    for (int i = 0; i < 4; i++) {
        int r = w * 4 + i;
        float s = 0.0f;
        #pragma unroll
        for (int e = 0; e < 32; e++) s = fmaf(qs[r][e], ks[lane][e], s);
        s *= scale;
        if (lane > r) s = -1e30f;   // causal mask

        float m = s;
        #pragma unroll
        for (int off = 16; off > 0; off >>= 1)
            m = fmaxf(m, __shfl_xor_sync(0xffffffffu, m, off));
        float p = __expf(s - m);
        float sum = p;
        #pragma unroll
        for (int off = 16; off > 0; off >>= 1)
            sum += __shfl_xor_sync(0xffffffffu, sum, off);
        float wei = p / sum;

        float a = 0.0f;
        #pragma unroll
        for (int ss = 0; ss < 32; ss++) {
            float wv = __shfl_sync(0xffffffffu, wei, ss);
            a = fmaf(wv, vs[ss][lane], a);
        }
        os[lane][r] = a;   // transpose in smem: [d][t]
    }
    __syncthreads();

    // Coalesced transposed write: g_at[(b*32+d)*512 + h*32 + t]
    for (int i = tid; i < NT * NHS; i += 256) {
        int d = i >> 5, t = i & 31;
        g_at[((size_t)(b * NHS + d)) * (NH * NT) + h * NT + t] = os[d][t];
    }
}

// ---------------------------------------------------------------------------
// Kernel C: final projection.  out[m,e] = sum_j AT[m,j]*Wp[e,j] + bp[e]
// Identical GEMM structure to kernel A; writes d_out ([B,HS,E]) directly.
// ---------------------------------------------------------------------------
__global__ __launch_bounds__(256) void proj_kernel(
    const float* __restrict__ Wp,
    const float* __restrict__ bp,
    float* __restrict__ out)
{
    __shared__ float As[8][128];
    __shared__ float Bs[8][128];

    const int tid = threadIdx.x;
    const int tx = tid & 15;
    const int ty = tid >> 4;
    const int m0 = blockIdx.y * 128;
    const int n0 = blockIdx.x * 128;

    const int lrow = tid >> 1;
    const int lk   = (tid & 1) * 4;

    const float* aptr = g_at + (size_t)(m0 + lrow) * NE + lk;
    const float* bptr = Wp   + (size_t)(n0 + lrow) * NE + lk;

    float acc[8][8];
    #pragma unroll
    for (int i = 0; i < 8; i++)
        #pragma unroll
        for (int j = 0; j < 8; j++) acc[i][j] = 0.0f;

    for (int k0 = 0; k0 < NE; k0 += 8) {
        float4 av = *(const float4*)(aptr + k0);
        float4 bv = *(const float4*)(bptr + k0);
        __syncthreads();
        As[lk + 0][lrow] = av.x; As[lk + 1][lrow] = av.y;
        As[lk + 2][lrow] = av.z; As[lk + 3][lrow] = av.w;
        Bs[lk + 0][lrow] = bv.x; Bs[lk + 1][lrow] = bv.y;
        Bs[lk + 2][lrow] = bv.z; Bs[lk + 3][lrow] = bv.w;
        __syncthreads();
        #pragma unroll
        for (int kk = 0; kk < 8; kk++) {
            float4 a0 = *(const float4*)&As[kk][ty * 8];
            float4 a1 = *(const float4*)&As[kk][ty * 8 + 4];
            float4 b0 = *(const float4*)&Bs[kk][tx * 8];
            float4 b1 = *(const float4*)&Bs[kk][tx * 8 + 4];
            float a[8] = {a0.x, a0.y, a0.z, a0.w, a1.x, a1.y, a1.z, a1.w};
            float b[8] = {b0.x, b0.y, b0.z, b0.w, b1.x, b1.y, b1.z, b1.w};
            #pragma unroll
            for (int i = 0; i < 8; i++)
                #pragma unroll
                for (int j = 0; j < 8; j++)
                    acc[i][j] = fmaf(a[i], b[j], acc[i][j]);
        }
    }

    #pragma unroll
    for (int i = 0; i < 8; i++) {
        int m = m0 + ty * 8 + i;
        #pragma unroll
        for (int j = 0; j < 8; j += 4) {
            int n = n0 + tx * 8 + j;
            float4 bb = *(const float4*)(bp + n);
            float4 v4 = make_float4(acc[i][j] + bb.x, acc[i][j+1] + bb.y,
                                    acc[i][j+2] + bb.z, acc[i][j+3] + bb.w);
            *(float4*)(out + (size_t)m * NE + n) = v4;
        }
    }
}

extern "C" void kernel_launch(void* const* d_in, const int* in_sizes, int n_in,
                              void* d_out, int out_size) {
    const float* x  = (const float*)d_in[0];
    const float* Wq = (const float*)d_in[1];
    const float* Wk = (const float*)d_in[2];
    const float* Wv = (const float*)d_in[3];
    const float* Wp = (const float*)d_in[4];
    const float* bp = (const float*)d_in[5];
    float* out = (float*)d_out;

    dim3 gA(NE / 128, NM / 128, 3);     // (4, 1024, 3)
    qkv_kernel<<<gA, 256>>>(x, Wq, Wk, Wv);

    attn_kernel<<<NB * NH, 256>>>();    // 65536 blocks

    dim3 gC(NE / 128, NM / 128, 1);     // (4, 1024)
    proj_kernel<<<gC, 256>>>(Wp, bp, out);
}

// round 5
// speedup vs baseline: 2.1892x; 2.1892x over previous
#include <cuda_runtime.h>
#include <cuda_bf16.h>
#include <cstdint>

#define NB 4096
#define NT 32
#define NH 16
#define NHS 32
#define NE 512
#define NM (NB*NT)          // 131072
#define KS 1536             // split-K concat x 512
#define KC 64               // k elems per chunk
#define NCHUNK (KS/KC)      // 24
#define CHUNK_BYTES 32768   // A 16KB + B 16KB
#define DSMEM (2*CHUNK_BYTES)

// fp32 scratch for attention
__device__ float g_q[(size_t)NB*NH*NT*NHS];
__device__ float g_k[(size_t)NB*NH*NT*NHS];
__device__ float g_v[(size_t)NB*NH*NT*NHS];
// split bf16 GEMM operands
__device__ __nv_bfloat16 g_xs[(size_t)NM*KS];    // A of QKV gemm   [hi|hi|lo]
__device__ __nv_bfloat16 g_as[(size_t)NM*KS];    // A of proj gemm  [hi|hi|lo]
__device__ __nv_bfloat16 g_bq[(size_t)KS*KS];    // B of QKV gemm   [hi|lo|hi]
__device__ __nv_bfloat16 g_bp[(size_t)NE*KS];    // B of proj gemm  [hi|lo|hi]

// ---------------------------------------------------------------------------
// helpers
// ---------------------------------------------------------------------------
__device__ __forceinline__ uint32_t sm2u(const void* p) {
    uint32_t a;
    asm("{ .reg .u64 t; cvta.to.shared.u64 t, %1; cvt.u32.u64 %0, t; }" : "=r"(a) : "l"(p));
    return a;
}

#define CPA16(sa, ga) asm volatile("cp.async.cg.shared.global [%0], [%1], 16;" :: "r"(sa), "l"(ga))
#define CPCOMMIT()    asm volatile("cp.async.commit_group;" ::: "memory")
#define CPWAIT1()     asm volatile("cp.async.wait_group 1;" ::: "memory")

#define LDM4(r0, r1, r2, r3, a) \
    asm volatile("ldmatrix.sync.aligned.m8n8.x4.shared.b16 {%0,%1,%2,%3}, [%4];" \
                 : "=r"(r0), "=r"(r1), "=r"(r2), "=r"(r3) : "r"(a))

#define MMA16816(d, a, b0, b1) \
    asm volatile("mma.sync.aligned.m16n8k16.row.col.f32.bf16.bf16.f32 " \
                 "{%0,%1,%2,%3}, {%4,%5,%6,%7}, {%8,%9}, {%0,%1,%2,%3};" \
                 : "+f"((d)[0]), "+f"((d)[1]), "+f"((d)[2]), "+f"((d)[3]) \
                 : "r"((a)[0]), "r"((a)[1]), "r"((a)[2]), "r"((a)[3]), "r"(b0), "r"(b1))

// ---------------------------------------------------------------------------
// Split / build kernels.
// A-operand rows (length 1536): [hi | hi | lo]
// B-operand rows (length 1536): [hi | lo | hi]
// so block-dot products give  hi*hi + hi*lo + lo*hi.
// ---------------------------------------------------------------------------
template <int BSIDE>
__device__ __forceinline__ void split4_store(__nv_bfloat16* row, int k, float4 v) {
    __nv_bfloat16 h0 = __float2bfloat16(v.x), h1 = __float2bfloat16(v.y);
    __nv_bfloat16 h2 = __float2bfloat16(v.z), h3 = __float2bfloat16(v.w);
    __nv_bfloat16 l0 = __float2bfloat16(v.x - __bfloat162float(h0));
    __nv_bfloat16 l1 = __float2bfloat16(v.y - __bfloat162float(h1));
    __nv_bfloat16 l2 = __float2bfloat16(v.z - __bfloat162float(h2));
    __nv_bfloat16 l3 = __float2bfloat16(v.w - __bfloat162float(h3));
    __nv_bfloat162 hA; hA.x = h0; hA.y = h1;
    __nv_bfloat162 hB; hB.x = h2; hB.y = h3;
    __nv_bfloat162 lA; lA.x = l0; lA.y = l1;
    __nv_bfloat162 lB; lB.x = l2; lB.y = l3;
    __nv_bfloat162* p0 = (__nv_bfloat162*)(row + k);
    __nv_bfloat162* p1 = (__nv_bfloat162*)(row + 512 + k);
    __nv_bfloat162* p2 = (__nv_bfloat162*)(row + 1024 + k);
    p0[0] = hA; p0[1] = hB;
    if (BSIDE) {               // B: [hi | lo | hi]
        p1[0] = lA; p1[1] = lB;
        p2[0] = hA; p2[1] = hB;
    } else {                   // A: [hi | hi | lo]
        p1[0] = hA; p1[1] = hB;
        p2[0] = lA; p2[1] = lB;
    }
}

__global__ __launch_bounds__(256) void split_x_kernel(const float4* __restrict__ x) {
    size_t i = (size_t)blockIdx.x * 256 + threadIdx.x;   // NM*NE/4 total
    float4 v = x[i];
    size_t m = i >> 7;
    int k = (int)(i & 127) * 4;
    split4_store<0>(g_xs + m * KS, k, v);
}

__global__ __launch_bounds__(256) void build_bq_kernel(const float4* __restrict__ Wq,
                                                       const float4* __restrict__ Wk,
                                                       const float4* __restrict__ Wv) {
    int i = blockIdx.x * 256 + threadIdx.x;              // 1536*128
    int n = i >> 7;
    int k = (i & 127) * 4;
    const float4* src = (n < 512) ? Wq : ((n < 1024) ? Wk : Wv);
    float4 v = src[(size_t)(n & 511) * 128 + (k >> 2)];
    split4_store<1>(g_bq + (size_t)n * KS, k, v);
}

__global__ __launch_bounds__(256) void build_bp_kernel(const float4* __restrict__ Wp) {
    int i = blockIdx.x * 256 + threadIdx.x;              // 512*128
    int n = i >> 7;
    int k = (i & 127) * 4;
    float4 v = Wp[(size_t)n * 128 + (k >> 2)];
    split4_store<1>(g_bp + (size_t)n * KS, k, v);
}

// ---------------------------------------------------------------------------
// HMMA bf16 GEMM:  C[m,n] = sum_k A[m,k]*B[n,k]   (both K-contiguous, K=1536)
// 128x128 CTA tile, 8 warps (2m x 4n), 64x32 warp tile, KC=64 double-buffered.
// MODE 0: A=g_xs, B=g_bq (N=1536), scatter to g_q/g_k/g_v [b,h,t,d]
// MODE 1: A=g_as, B=g_bp (N=512),  out[m*512+n] + bp[n]
// ---------------------------------------------------------------------------
__device__ __forceinline__ void load_chunk(const char* __restrict__ Ab,
                                           const char* __restrict__ Bb,
                                           int tid, int c, uint32_t stage_base) {
    #pragma unroll
    for (int j = 0; j < 4; j++) {                 // A: 1024 x 16B segs
        int q = tid + j * 256;
        int row = q >> 3, s16 = q & 7;
        uint32_t off = row * 128 + s16 * 16;
        uint32_t sa = stage_base + (off ^ ((off >> 3) & 0x70));
        CPA16(sa, Ab + (size_t)row * (KS * 2) + c * 128 + s16 * 16);
    }
    #pragma unroll
    for (int j = 0; j < 4; j++) {                 // B: 1024 x 16B segs
        int q = tid + j * 256;
        int row = q >> 3, s16 = q & 7;
        uint32_t off = row * 128 + s16 * 16;
        uint32_t sb = stage_base + 16384 + (off ^ ((off >> 3) & 0x70));
        CPA16(sb, Bb + (size_t)row * (KS * 2) + c * 128 + s16 * 16);
    }
}

template <int MODE>
__global__ __launch_bounds__(256) void gemm_kernel(const float* __restrict__ bp,
                                                   float* __restrict__ outp) {
    extern __shared__ char smem[];
    const __nv_bfloat16* A  = (MODE == 0) ? g_xs : g_as;
    const __nv_bfloat16* Bw = (MODE == 0) ? g_bq : g_bp;

    const int tid = threadIdx.x;
    const int wid = tid >> 5, lane = tid & 31;
    const int m0 = blockIdx.y * 128;
    const int n0 = blockIdx.x * 128;
    const uint32_t s0 = sm2u(smem);

    const char* Ab = (const char*)A + (size_t)m0 * (KS * 2);
    const char* Bb = (const char*)Bw + (size_t)n0 * (KS * 2);

    float acc[4][4][4];
    #pragma unroll
    for (int i = 0; i < 4; i++)
        #pragma unroll
        for (int j = 0; j < 4; j++)
            #pragma unroll
            for (int k = 0; k < 4; k++) acc[i][j][k] = 0.0f;

    const int lj = lane >> 3, lr = lane & 7;
    const int rowA0 = (wid & 1) * 64 + (lj & 1) * 8 + lr;   // + mf*16
    const int rowB0 = (wid >> 1) * 32 + (lj & 1) * 8 + lr;  // + nf2*16
    const int colj = (lj >> 1) * 16;                        // + ks*32

    load_chunk(Ab, Bb, tid, 0, s0); CPCOMMIT();
    load_chunk(Ab, Bb, tid, 1, s0 + CHUNK_BYTES); CPCOMMIT();

    #pragma unroll 1
    for (int c = 0; c < NCHUNK; c++) {
        const uint32_t aS = s0 + (c & 1) * CHUNK_BYTES;
        const uint32_t bS = aS + 16384;
        CPWAIT1();
        __syncthreads();

        #pragma unroll
        for (int ks = 0; ks < 4; ks++) {
            const int cb = ks * 32 + colj;
            uint32_t a[4][4], b[2][4];
            #pragma unroll
            for (int mf = 0; mf < 4; mf++) {
                int row = rowA0 + mf * 16;
                uint32_t ad = aS + row * 128 + (cb ^ ((row & 7) << 4));
                LDM4(a[mf][0], a[mf][1], a[mf][2], a[mf][3], ad);
            }
            #pragma unroll
            for (int nf2 = 0; nf2 < 2; nf2++) {
                int row = rowB0 + nf2 * 16;
                uint32_t bd = bS + row * 128 + (cb ^ ((row & 7) << 4));
                LDM4(b[nf2][0], b[nf2][1], b[nf2][2], b[nf2][3], bd);
            }
            #pragma unroll
            for (int mf = 0; mf < 4; mf++) {
                #pragma unroll
                for (int nf = 0; nf < 4; nf++) {
                    uint32_t b0 = (nf & 1) ? b[nf >> 1][1] : b[nf >> 1][0];
                    uint32_t b1 = (nf & 1) ? b[nf >> 1][3] : b[nf >> 1][2];
                    MMA16816(acc[mf][nf], a[mf], b0, b1);
                }
            }
        }

        __syncthreads();
        if (c + 2 < NCHUNK) load_chunk(Ab, Bb, tid, c + 2, aS);
        CPCOMMIT();
    }

    // epilogue
    const int g = lane >> 2, tig = lane & 3;
    #pragma unroll
    for (int mf = 0; mf < 4; mf++) {
        #pragma unroll
        for (int nf = 0; nf < 4; nf++) {
            int n = n0 + (wid >> 1) * 32 + nf * 8 + tig * 2;
            #pragma unroll
            for (int half = 0; half < 2; half++) {
                int m = m0 + (wid & 1) * 64 + mf * 16 + g + half * 8;
                float2 v2 = make_float2(acc[mf][nf][half * 2], acc[mf][nf][half * 2 + 1]);
                if (MODE == 0) {
                    int b = m >> 5, t = m & 31;
                    int which = n >> 9, h = (n >> 5) & 15, d = n & 31;
                    float* dst = ((which == 0) ? g_q : (which == 1) ? g_k : g_v)
                                 + (((size_t)(b * NH + h) * NT + t) * NHS + d);
                    *(float2*)dst = v2;
                } else {
                    v2.x += bp[n]; v2.y += bp[n + 1];
                    *(float2*)(outp + (size_t)m * NE + n) = v2;
                }
            }
        }
    }
}

// ---------------------------------------------------------------------------
// Attention: per-(b,h) 32x32x32 causal softmax, fp32; output split-bf16,
// transposed (A-operand convention [hi|hi|lo]):
//   g_as[(b*32+d)*1536 + h*32+t | +512 | +1024]
// ---------------------------------------------------------------------------
__global__ __launch_bounds__(256) void attn_kernel() {
    __shared__ float qs[32][33];
    __shared__ float ks[32][33];
    __shared__ float vs[32][33];
    __shared__ float os[32][33];   // [d][t]

    const int bh = blockIdx.x;
    const int b = bh >> 4, h = bh & 15;
    const int tid = threadIdx.x;
    const size_t base = (size_t)bh * NT * NHS;

    for (int i = tid; i < NT * NHS; i += 256) {
        int t = i >> 5, d = i & 31;
        qs[t][d] = g_q[base + i];
        ks[t][d] = g_k[base + i];
        vs[t][d] = g_v[base + i];
    }
    __syncthreads();

    const int w = tid >> 5, lane = tid & 31;
    const float scale = 0.17677669529663687f;   // 1/sqrt(32)

    #pragma unroll
    for (int i = 0; i < 4; i++) {
        int r = w * 4 + i;
        float s = 0.0f;
        #pragma unroll
        for (int e = 0; e < 32; e++) s = fmaf(qs[r][e], ks[lane][e], s);
        s *= scale;
        if (lane > r) s = -1e30f;

        float mx = s;
        #pragma unroll
        for (int off = 16; off > 0; off >>= 1)
            mx = fmaxf(mx, __shfl_xor_sync(0xffffffffu, mx, off));
        float pp = __expf(s - mx);
        float sum = pp;
        #pragma unroll
        for (int off = 16; off > 0; off >>= 1)
            sum += __shfl_xor_sync(0xffffffffu, sum, off);
        float wei = pp / sum;

        float a = 0.0f;
        #pragma unroll
        for (int ss = 0; ss < 32; ss++) {
            float wv = __shfl_sync(0xffffffffu, wei, ss);
            a = fmaf(wv, vs[ss][lane], a);
        }
        os[lane][r] = a;
    }
    __syncthreads();

    for (int i = tid; i < NT * NHS; i += 256) {
        int d = i >> 5, t = i & 31;
        float val = os[d][t];
        __nv_bfloat16 hi = __float2bfloat16(val);
        __nv_bfloat16 lo = __float2bfloat16(val - __bfloat162float(hi));
        size_t rb = (size_t)(b * NHS + d) * KS + h * NT + t;
        g_as[rb]        = hi;
        g_as[rb + 512]  = hi;
        g_as[rb + 1024] = lo;
    }
}

// ---------------------------------------------------------------------------
extern "C" void kernel_launch(void* const* d_in, const int* in_sizes, int n_in,
                              void* d_out, int out_size) {
    const float* x  = (const float*)d_in[0];
    const float* Wq = (const float*)d_in[1];
    const float* Wk = (const float*)d_in[2];
    const float* Wv = (const float*)d_in[3];
    const float* Wp = (const float*)d_in[4];
    const float* bp = (const float*)d_in[5];
    float* out = (float*)d_out;

    cudaFuncSetAttribute(gemm_kernel<0>, cudaFuncAttributeMaxDynamicSharedMemorySize, DSMEM);
    cudaFuncSetAttribute(gemm_kernel<1>, cudaFuncAttributeMaxDynamicSharedMemorySize, DSMEM);

    split_x_kernel<<<(NM * NE / 4) / 256, 256>>>((const float4*)x);
    build_bq_kernel<<<(KS * 128) / 256, 256>>>((const float4*)Wq, (const float4*)Wk, (const float4*)Wv);
    build_bp_kernel<<<(NE * 128) / 256, 256>>>((const float4*)Wp);

    gemm_kernel<0><<<dim3(KS / 128, NM / 128), 256, DSMEM>>>(nullptr, nullptr);
    attn_kernel<<<NB * NH, 256>>>();
    gemm_kernel<1><<<dim3(NE / 128, NM / 128), 256, DSMEM>>>(bp, out);
}